// round 17
// baseline (speedup 1.0000x reference)
#include <cuda_runtime.h>
#include <cuda_bf16.h>
#include <cstdint>

#define BATCH 1024
#define SEQL  200
#define DIM   128

// Scratch (allocation-free rule: __device__ globals)
// Xb layout: [64 ksteps][128 n][4 tig] uint4 = {b0hi, b1hi, b0lo, b1lo}
// (bf16x2 each). kstep covers k = ks*16 .. ks*16+15; within a fragment:
//   b0 = rows 2*tig,2*tig+1; b1 = rows 2*tig+8,2*tig+9; col = gid.
__device__ unsigned xb0_buf[64 * 128 * 16];        // g   (512 KB)
__device__ unsigned xb1_buf[64 * 128 * 16];        // ag  (512 KB)
__device__ float    part_buf[4 * BATCH * DIM];     // 4 K-split partials (2 MB)
__device__ int      cntA_buf[32];                  // last-block counters
__device__ int      cntD_buf[32];

// ---------------------------------------------------------------------------
// bf16 split helpers (Ootomo 3-product scheme: hh + hl + lh)
// ---------------------------------------------------------------------------
__device__ __forceinline__ void bf16_split(float v, unsigned short& h, unsigned short& l) {
    __nv_bfloat16 hb = __float2bfloat16(v);
    __nv_bfloat16 lb = __float2bfloat16(v - __bfloat162float(hb));
    h = *(unsigned short*)&hb;
    l = *(unsigned short*)&lb;
}
// split a float2 (k-even, k-odd) into packed hi-uint and lo-uint
__device__ __forceinline__ void split2(float2 f, unsigned& h, unsigned& l) {
    unsigned short h0, l0, h1, l1;
    bf16_split(f.x, h0, l0);
    bf16_split(f.y, h1, l1);
    h = (unsigned)h0 | ((unsigned)h1 << 16);
    l = (unsigned)l0 | ((unsigned)l1 << 16);
}
__device__ __forceinline__ void mma_bf16(float c[4],
                                         const unsigned a[4],
                                         unsigned b0, unsigned b1) {
    asm volatile(
        "mma.sync.aligned.m16n8k16.row.col.f32.bf16.bf16.f32 "
        "{%0,%1,%2,%3}, {%4,%5,%6,%7}, {%8,%9}, {%0,%1,%2,%3};"
        : "+f"(c[0]), "+f"(c[1]), "+f"(c[2]), "+f"(c[3])
        : "r"(a[0]), "r"(a[1]), "r"(a[2]), "r"(a[3]), "r"(b0), "r"(b1));
}

// Write one value of X[k][n] into the Xb fragment layout (hi/lo bf16).
__device__ __forceinline__ void xb_write(unsigned* xb, int k, int n, float v) {
    const int ks  = k >> 4;
    const int r   = k & 15;
    const int reg = (r >= 8) ? 1 : 0;
    const int rr  = r & 7;
    const int tig = rr >> 1;
    const int e   = rr & 1;
    unsigned short h, l; bf16_split(v, h, l);
    unsigned short* s = (unsigned short*)(xb + (((ks * 128 + n) * 4 + tig) << 2));
    s[reg * 2 + e]     = h;   // uint4.x/.y
    s[4 + reg * 2 + e] = l;   // uint4.z/.w
}

// ---------------------------------------------------------------------------
// Kernel 1: g[b] = sum_l item_embedding[items[b,l]]; writes Xb frag layout.
// Also zeroes the last-block counters for both GEMMs (block 0).
// (DRAM-saturated random gather: ~86 MB compulsory @ ~3.9-4 TB/s.)
// ---------------------------------------------------------------------------
__global__ void __launch_bounds__(256) gather_sum_kernel(
    const float* __restrict__ emb,
    const void* __restrict__ items_raw,
    unsigned* __restrict__ xb,
    int* __restrict__ cntA,
    int* __restrict__ cntD)
{
    const int b    = blockIdx.x;
    const int t    = threadIdx.x;
    const int w    = t >> 5;
    const int lane = t & 31;

    if (b == 0 && t < 64) {
        if (t < 32) cntA[t] = 0;
        else        cntD[t - 32] = 0;
    }

    __shared__ int sidx[SEQL];
    __shared__ int mode64;
    __shared__ float4 spart[8][32];

    if (t == 0) {
        // int64 storage => odd int32 words of first 16 elements are all zero
        const int* p = (const int*)items_raw;
        int ok = 1;
        #pragma unroll
        for (int i = 0; i < 16; i++) ok &= (p[2 * i + 1] == 0);
        mode64 = ok;
    }
    __syncthreads();

    if (t < SEQL) {
        if (mode64) sidx[t] = (int)((const long long*)items_raw)[(long long)b * SEQL + t];
        else        sidx[t] = ((const int*)items_raw)[b * SEQL + t];
    }
    __syncthreads();

    float4 acc[5], v[5];
    #pragma unroll
    for (int j = 0; j < 5; j++) acc[j] = make_float4(0.f, 0.f, 0.f, 0.f);

    #pragma unroll
    for (int j = 0; j < 5; j++)
        v[j] = *(const float4*)&emb[(size_t)sidx[w + 8 * j] * DIM + lane * 4];

    #pragma unroll
    for (int s = 0; s < 5; s++) {
        float4 nv[5];
        if (s < 4) {
            #pragma unroll
            for (int j = 0; j < 5; j++)
                nv[j] = *(const float4*)&emb[(size_t)sidx[w + 8 * (5 * (s + 1) + j)] * DIM + lane * 4];
        }
        #pragma unroll
        for (int j = 0; j < 5; j++) {
            acc[j].x += v[j].x; acc[j].y += v[j].y;
            acc[j].z += v[j].z; acc[j].w += v[j].w;
        }
        if (s < 4) {
            #pragma unroll
            for (int j = 0; j < 5; j++) v[j] = nv[j];
        }
    }

    float4 s4;
    s4.x = ((acc[0].x + acc[1].x) + (acc[2].x + acc[3].x)) + acc[4].x;
    s4.y = ((acc[0].y + acc[1].y) + (acc[2].y + acc[3].y)) + acc[4].y;
    s4.z = ((acc[0].z + acc[1].z) + (acc[2].z + acc[3].z)) + acc[4].z;
    s4.w = ((acc[0].w + acc[1].w) + (acc[2].w + acc[3].w)) + acc[4].w;

    spart[w][lane] = s4;
    __syncthreads();
    if (w < 4) {
        float4 a = spart[w][lane], c = spart[w + 4][lane];
        a.x += c.x; a.y += c.y; a.z += c.z; a.w += c.w;
        spart[w][lane] = a;
    }
    __syncthreads();
    if (w < 2) {
        float4 a = spart[w][lane], c = spart[w + 2][lane];
        a.x += c.x; a.y += c.y; a.z += c.z; a.w += c.w;
        spart[w][lane] = a;
    }
    __syncthreads();
    if (w == 0) {
        float4 a = spart[0][lane], c = spart[1][lane];
        a.x += c.x; a.y += c.y; a.z += c.z; a.w += c.w;
        const float av[4] = {a.x, a.y, a.z, a.w};
        #pragma unroll
        for (int j = 0; j < 4; j++)
            xb_write(xb, b, lane * 4 + j, av[j]);
    }
}

// ---------------------------------------------------------------------------
// Kernel 2: tensor-core 3xBF16 (Ootomo) GEMM (BM=32, K-split=4) with FUSED
// cross-split reduction via last-block epilogue:
//   MODE 0: last block per m-group converts reduced rows to Xb (feeds gemmD)
//   MODE 1: last block per m-group does selu + row L2-norm -> final output
// grid = 128 blocks (32 m-groups x 4 K-splits) = ONE wave, 512 threads
// (16 warps = 4/SMSP). Warp (wk = warp>>3, wn = warp&7): n-slice wn*16,
// kstep half wk; cross-k-half reduction through smem.
//
// Prologue: DIRECT gmem->fragment conversion, ONE sync:
//   per tuple (ks,mt,lane): 4x LDG.64 (A[r0/r1][col], [col+8]) -> split in
//   regs -> 2x STS.128. col = k0 + ks*16 + 2*tig (identical algebra to the
//   verified two-half staging; staging buffer + 4 syncs removed).
// ---------------------------------------------------------------------------
template <int MODE>
__global__ void __launch_bounds__(512) gemm_tc_kernel(
    const float* __restrict__ A,
    const uint4* __restrict__ Xb,    // [64 ksteps][128 n][4 tig]
    float* __restrict__ part,
    int* __restrict__ cnt,
    void* __restrict__ outv)
{
    const int mg    = blockIdx.x >> 2;   // 0..31
    const int split = blockIdx.x & 3;    // 0..3
    const int m0 = mg * 32;
    const int k0 = split * 256;

    __shared__ __align__(16) unsigned sAfh[16][2][32][4];   // 16 KB
    __shared__ __align__(16) unsigned sAfl[16][2][32][4];   // 16 KB
    __shared__ __align__(16) float    redf[4096];           // 16 KB cross-k-half
    __shared__ int s_done;

    const int tid = threadIdx.x;

    // ---- prologue: direct LDG -> split -> fragment STS (1024 tuples) ----
    {
        float2 f[2][4];
        int    tks[2], tmt[2], tlane[2];
        #pragma unroll
        for (int j = 0; j < 2; j++) {
            const int idx  = tid + 512 * j;
            const int lane = idx & 31;
            const int mt   = (idx >> 5) & 1;
            const int ks   = idx >> 6;           // 0..15
            const int gid8 = lane >> 2;
            const int tig  = lane & 3;
            const int r0   = m0 + mt * 16 + gid8;
            const int col  = k0 + ks * 16 + 2 * tig;
            tks[j] = ks; tmt[j] = mt; tlane[j] = lane;
            f[j][0] = *(const float2*)&A[(size_t)r0 * 1024 + col];          // row lo, k lo
            f[j][1] = *(const float2*)&A[(size_t)(r0 + 8) * 1024 + col];    // row hi, k lo
            f[j][2] = *(const float2*)&A[(size_t)r0 * 1024 + col + 8];      // row lo, k hi
            f[j][3] = *(const float2*)&A[(size_t)(r0 + 8) * 1024 + col + 8];// row hi, k hi
        }
        #pragma unroll
        for (int j = 0; j < 2; j++) {
            uint4 hv, lv;
            split2(f[j][0], hv.x, lv.x);
            split2(f[j][1], hv.y, lv.y);
            split2(f[j][2], hv.z, lv.z);
            split2(f[j][3], hv.w, lv.w);
            *(uint4*)&sAfh[tks[j]][tmt[j]][tlane[j]][0] = hv;
            *(uint4*)&sAfl[tks[j]][tmt[j]][tlane[j]][0] = lv;
        }
    }
    __syncthreads();

    const int lane = tid & 31;
    const int warp = tid >> 5;   // 0..15
    const int wk   = warp >> 3;  // kstep half: 0 -> ks 0..7, 1 -> ks 8..15
    const int wn   = warp & 7;   // n-slice
    const int gid  = lane >> 2;
    const int tig  = lane & 3;
    const int nb   = wn * 16;
    const int ksbase = wk * 8;

    float chh[2][2][4], cor[2][2][4];
    #pragma unroll
    for (int mt = 0; mt < 2; mt++)
        #pragma unroll
        for (int nt = 0; nt < 2; nt++)
            #pragma unroll
            for (int i = 0; i < 4; i++) { chh[mt][nt][i] = 0.f; cor[mt][nt][i] = 0.f; }

    const uint4* Xq = Xb + (size_t)(split * 16) * 128 * 4;
    const int n0 = nb + gid;
    const int n1 = nb + 8 + gid;

    // ring prefetch: 4 ksteps deep (of this warp's 8)
    uint4 br[4][2];
    #pragma unroll
    for (int q = 0; q < 4; q++) {
        br[q][0] = Xq[((ksbase + q) * 128 + n0) * 4 + tig];
        br[q][1] = Xq[((ksbase + q) * 128 + n1) * 4 + tig];
    }

    #pragma unroll
    for (int ksb = 0; ksb < 8; ksb += 4) {
        #pragma unroll
        for (int q = 0; q < 4; q++) {
            const int ksl = ksb + q;              // 0..7 local
            const int ks  = ksbase + ksl;         // smem kstep index
            uint4 ah4[2], al4[2];
            #pragma unroll
            for (int mt = 0; mt < 2; mt++) {
                ah4[mt] = *(const uint4*)&sAfh[ks][mt][lane][0];
                al4[mt] = *(const uint4*)&sAfl[ks][mt][lane][0];
            }
            #pragma unroll
            for (int nt = 0; nt < 2; nt++) {
                const uint4 b = br[q][nt];
                #pragma unroll
                for (int mt = 0; mt < 2; mt++) {
                    const unsigned ah[4] = {ah4[mt].x, ah4[mt].y, ah4[mt].z, ah4[mt].w};
                    const unsigned al[4] = {al4[mt].x, al4[mt].y, al4[mt].z, al4[mt].w};
                    mma_bf16(chh[mt][nt], ah, b.x, b.y);   // hi*hi
                    mma_bf16(cor[mt][nt], ah, b.z, b.w);   // hi*lo
                    mma_bf16(cor[mt][nt], al, b.x, b.y);   // lo*hi
                }
            }
            if (ksl + 4 < 8) {
                br[q][0] = Xq[((ks + 4) * 128 + n0) * 4 + tig];
                br[q][1] = Xq[((ks + 4) * 128 + n1) * 4 + tig];
            }
        }
    }

    // ---- cross-k-half reduction through smem ----
    __syncthreads();
    if (wk == 1) {
        #pragma unroll
        for (int mt = 0; mt < 2; mt++)
            #pragma unroll
            for (int nt = 0; nt < 2; nt++)
                #pragma unroll
                for (int i = 0; i < 4; i++)
                    redf[((((wn * 2 + mt) * 2 + nt) * 32) + lane) * 4 + i] =
                        chh[mt][nt][i] + cor[mt][nt][i];
    }
    __syncthreads();

    if (wk == 0) {
        float* pb = part + (size_t)split * BATCH * DIM;
        #pragma unroll
        for (int mt = 0; mt < 2; mt++) {
            const int r = m0 + mt * 16 + gid;
            #pragma unroll
            for (int nt = 0; nt < 2; nt++) {
                const int n = nb + nt * 8 + 2 * tig;
                const float* rf = &redf[((((wn * 2 + mt) * 2 + nt) * 32) + lane) * 4];
                pb[r * DIM + n]           = chh[mt][nt][0] + cor[mt][nt][0] + rf[0];
                pb[r * DIM + n + 1]       = chh[mt][nt][1] + cor[mt][nt][1] + rf[1];
                pb[(r + 8) * DIM + n]     = chh[mt][nt][2] + cor[mt][nt][2] + rf[2];
                pb[(r + 8) * DIM + n + 1] = chh[mt][nt][3] + cor[mt][nt][3] + rf[3];
            }
        }
    }

    // ---- fused cross-split reduction: last block of this m-group ----
    __threadfence();
    __syncthreads();
    if (tid == 0) s_done = (atomicAdd(&cnt[mg], 1) == 3);
    __syncthreads();
    if (!s_done) return;
    __threadfence();

    // 32 rows x 128 cols; warp handles 2 rows, lane covers 4 cols (float4)
    #pragma unroll
    for (int i = 0; i < 2; i++) {
        const int row = m0 + warp * 2 + i;
        float4 s = make_float4(0.f, 0.f, 0.f, 0.f);
        #pragma unroll
        for (int sp = 0; sp < 4; sp++) {
            const float4 p = *(const float4*)&part[((size_t)sp * BATCH + row) * DIM + lane * 4];
            s.x += p.x; s.y += p.y; s.z += p.z; s.w += p.w;
        }
        if (MODE == 0) {
            unsigned* xo = (unsigned*)outv;
            xb_write(xo, row, lane * 4 + 0, s.x);
            xb_write(xo, row, lane * 4 + 1, s.y);
            xb_write(xo, row, lane * 4 + 2, s.z);
            xb_write(xo, row, lane * 4 + 3, s.w);
        } else {
            const float SELU_SCALE = 1.0507009873554804934f;
            const float SELU_ALPHA = 1.6732632423543772848f;
            float4 sv;
            sv.x = (s.x > 0.f) ? SELU_SCALE * s.x : SELU_SCALE * SELU_ALPHA * (expf(s.x) - 1.f);
            sv.y = (s.y > 0.f) ? SELU_SCALE * s.y : SELU_SCALE * SELU_ALPHA * (expf(s.y) - 1.f);
            sv.z = (s.z > 0.f) ? SELU_SCALE * s.z : SELU_SCALE * SELU_ALPHA * (expf(s.z) - 1.f);
            sv.w = (s.w > 0.f) ? SELU_SCALE * s.w : SELU_SCALE * SELU_ALPHA * (expf(s.w) - 1.f);
            float sq = sv.x * sv.x + sv.y * sv.y + sv.z * sv.z + sv.w * sv.w;
            #pragma unroll
            for (int o = 16; o; o >>= 1) sq += __shfl_xor_sync(0xFFFFFFFFu, sq, o);
            const float inv = rsqrtf(sq);
            float* o = (float*)outv;
            *(float4*)&o[row * DIM + lane * 4] =
                make_float4(sv.x * inv, sv.y * inv, sv.z * inv, sv.w * inv);
        }
    }
}

// ---------------------------------------------------------------------------
// Launch: gather(->Xb, zero counters) -> gemmA(+convert to Xb) ->
//         gemmD(+selu+norm). 3 kernels total.
// (attention/entmax path is analytically identity on g: scores constant
//  along L, entmax of a constant is uniform, sum(p)*g = g)
// ---------------------------------------------------------------------------
extern "C" void kernel_launch(void* const* d_in, const int* in_sizes, int n_in,
                              void* d_out, int out_size)
{
    const float* emb   = (const float*)d_in[0];  // [500000, 128]
    const void*  items = d_in[1];                // [1024, 200] int64/int32
    const float* Amat  = (const float*)d_in[2];  // [1024, 1024]
    const float* Dmat  = (const float*)d_in[3];  // [1024, 1024]
    float* out = (float*)d_out;                  // [1024, 128]

    unsigned *xb0, *xb1;
    float *part;
    int *cntA, *cntD;
    cudaGetSymbolAddress((void**)&xb0, xb0_buf);
    cudaGetSymbolAddress((void**)&xb1, xb1_buf);
    cudaGetSymbolAddress((void**)&part, part_buf);
    cudaGetSymbolAddress((void**)&cntA, cntA_buf);
    cudaGetSymbolAddress((void**)&cntD, cntD_buf);

    gather_sum_kernel<<<BATCH, 256>>>(emb, items, xb0, cntA, cntD);

    gemm_tc_kernel<0><<<128, 512>>>(Amat, (const uint4*)xb0, part, cntA, xb1);
    gemm_tc_kernel<1><<<128, 512>>>(Dmat, (const uint4*)xb1, part, cntD, out);
}